// round 7
// baseline (speedup 1.0000x reference)
#include <cuda_runtime.h>

#define N_NODES 100000
#define N_EDGES 1600000
#define NFEAT   128
#define NHID    64
#define CAP     64              // padded bucket capacity per row (max degree ~45)

// ---- scratch (__device__ globals: zero-initialized at module load) ---------
__device__ float              g_support[N_NODES * NHID];     // 25.6 MB
__device__ int                g_cnt[N_NODES];                 // cursor; re-zeroed by reduce
__device__ unsigned long long g_edges[N_NODES * CAP];         // 51.2 MB padded buckets

// ---------------------------------------------------------------------------
// JAX partitionable threefry2x32, key (0,42), count (0, i): returns out0^out1
// ---------------------------------------------------------------------------
__device__ __forceinline__ unsigned tf_hash(unsigned i) {
    const unsigned ks0 = 0u, ks1 = 42u, ks2 = 0x1BD11BF0u;  // 0 ^ 42 ^ 0x1BD11BDA
    unsigned x0 = ks0;        // counts_hi = 0
    unsigned x1 = i + ks1;    // counts_lo = i
#define TFR(r) { x0 += x1; x1 = __funnelshift_l(x1, x1, (r)); x1 ^= x0; }
    TFR(13) TFR(15) TFR(26) TFR(6)   x0 += ks1; x1 += ks2 + 1u;
    TFR(17) TFR(29) TFR(16) TFR(24)  x0 += ks2; x1 += ks0 + 2u;
    TFR(13) TFR(15) TFR(26) TFR(6)   x0 += ks0; x1 += ks1 + 3u;
    TFR(17) TFR(29) TFR(16) TFR(24)  x0 += ks1; x1 += ks2 + 4u;
    TFR(13) TFR(15) TFR(26) TFR(6)   x0 += ks2; x1 += ks0 + 5u;
#undef TFR
    return x0 ^ x1;
}

// ---------------------------------------------------------------------------
// Bucket build: one pass, no scan. idx = row*CAP + atomic cursor.
// Runs FIRST so its L2 traffic is displaced by gemm before reduce runs.
// ---------------------------------------------------------------------------
__global__ __launch_bounds__(256) void build_kernel(const int*   __restrict__ erow,
                                                    const int*   __restrict__ ecol,
                                                    const float* __restrict__ ev) {
    int e = blockIdx.x * 256 + threadIdx.x;
    if (e >= N_EDGES) return;
    int   r = erow[e];
    int   c = ecol[e];
    float v = ev[e];
    int pos = atomicAdd(&g_cnt[r], 1);
    if (pos < CAP)   // statistically impossible to overflow; guard vs corruption
        g_edges[r * CAP + pos] =
            ((unsigned long long)__float_as_uint(v) << 32) | (unsigned)c;
}

// ---------------------------------------------------------------------------
// GEMM: support[100000,64] = x[100000,128] @ W[128,64]
// Tile 256 rows x 64 cols, 256 threads, K-chunks of 32; 8x8 per thread.
// Runs LAST before reduce: support freshest in L2.
// ---------------------------------------------------------------------------
__global__ __launch_bounds__(256, 2) void gemm_kernel(const float* __restrict__ x,
                                                      const float* __restrict__ W) {
    __shared__ float Xs[256][33];
    __shared__ float Ws[32][64];
    const int tid  = threadIdx.x;
    const int lane = tid & 31;
    const int tx   = tid >> 5;
    const int bm   = blockIdx.x * 256;

    float acc[8][8];
#pragma unroll
    for (int j = 0; j < 8; j++)
#pragma unroll
        for (int n = 0; n < 8; n++) acc[j][n] = 0.f;

    for (int kc = 0; kc < 4; kc++) {
#pragma unroll
        for (int i = 0; i < 8; i++) {
            int fi  = tid + i * 256;
            int row = fi >> 3;
            int kq  = fi & 7;
            int grow = bm + row;
            float4 v = make_float4(0.f, 0.f, 0.f, 0.f);
            if (grow < N_NODES)
                v = reinterpret_cast<const float4*>(x)[grow * 32 + kc * 8 + kq];
            Xs[row][kq * 4 + 0] = v.x;
            Xs[row][kq * 4 + 1] = v.y;
            Xs[row][kq * 4 + 2] = v.z;
            Xs[row][kq * 4 + 3] = v.w;
        }
#pragma unroll
        for (int i = 0; i < 2; i++) {
            int fi = tid + i * 256;
            int kk = fi >> 4;
            int nq = fi & 15;
            reinterpret_cast<float4*>(&Ws[kk][nq * 4])[0] =
                reinterpret_cast<const float4*>(W)[(kc * 32 + kk) * 16 + nq];
        }
        __syncthreads();

#pragma unroll 4
        for (int k = 0; k < 32; k++) {
            float4 b0 = *reinterpret_cast<const float4*>(&Ws[k][tx * 8]);
            float4 b1 = *reinterpret_cast<const float4*>(&Ws[k][tx * 8 + 4]);
#pragma unroll
            for (int j = 0; j < 8; j++) {
                float a = Xs[lane + 32 * j][k];
                acc[j][0] += a * b0.x; acc[j][1] += a * b0.y;
                acc[j][2] += a * b0.z; acc[j][3] += a * b0.w;
                acc[j][4] += a * b1.x; acc[j][5] += a * b1.y;
                acc[j][6] += a * b1.z; acc[j][7] += a * b1.w;
            }
        }
        __syncthreads();
    }

#pragma unroll
    for (int j = 0; j < 8; j++) {
        int r = bm + lane + 32 * j;
        if (r < N_NODES) {
            float4* dst = reinterpret_cast<float4*>(&g_support[r * 64 + tx * 8]);
            dst[0] = make_float4(acc[j][0], acc[j][1], acc[j][2], acc[j][3]);
            dst[1] = make_float4(acc[j][4], acc[j][5], acc[j][6], acc[j][7]);
        }
    }
}

// ---------------------------------------------------------------------------
// Gather-reduce + fused epilogue: HALF-WARP per row, float4 per lane.
// Lanes 0-15 -> row r0, lanes 16-31 -> r1. One gather per iter serves 2 edges
// (512B). Loop runs to max(deg0,deg1) with predicated zero-contributions:
// no remainder loops, R4-simple control flow. Resets g_cnt for next call.
// ---------------------------------------------------------------------------
__global__ __launch_bounds__(256) void reduce_kernel(float* __restrict__ out,
                                                     const float* __restrict__ bias) {
    const int lane  = threadIdx.x & 31;
    const int hlane = lane & 15;              // feature chunk within row
    const int wid   = threadIdx.x >> 5;
    const int r0    = blockIdx.x * 16 + wid * 2;   // grid 6250 -> exact
    const int r1    = r0 + 1;
    const int myrow = (lane < 16) ? r0 : r1;

    int deg0 = g_cnt[r0];
    int deg1 = g_cnt[r1];
    if (lane == 0) { g_cnt[r0] = 0; g_cnt[r1] = 0; }    // reset for next call
    if (deg0 > CAP) deg0 = CAP;
    if (deg1 > CAP) deg1 = CAP;
    const int mydeg = (lane < 16) ? deg0 : deg1;

    // one coalesced 256B edge-word load per row
    unsigned long long ew0 = g_edges[(size_t)r0 * CAP + lane];
    unsigned long long ew1 = g_edges[(size_t)r1 * CAP + lane];

    const float4* sup4 = reinterpret_cast<const float4*>(g_support);
    float4 acc = make_float4(0.f, 0.f, 0.f, 0.f);

    int nb0 = deg0 < 32 ? deg0 : 32;
    int nb1 = deg1 < 32 ? deg1 : 32;
    int mynb = (lane < 16) ? nb0 : nb1;
    int nmax = nb0 > nb1 ? nb0 : nb1;

#pragma unroll 4
    for (int j = 0; j < nmax; j++) {
        unsigned long long e0 = __shfl_sync(0xFFFFFFFFu, ew0, j);
        unsigned long long e1 = __shfl_sync(0xFFFFFFFFu, ew1, j);
        unsigned long long e  = (lane < 16) ? e0 : e1;
        bool act = j < mynb;
        unsigned c = act ? (unsigned)e : 0u;
        float    v = act ? __uint_as_float((unsigned)(e >> 32)) : 0.f;
        float4 s = sup4[c * 16u + hlane];
        acc.x += v * s.x; acc.y += v * s.y;
        acc.z += v * s.z; acc.w += v * s.w;
    }
    if (deg0 > 32 || deg1 > 32) {             // rare tail (P ~ 1e-4 of rows)
        unsigned long long eh0 = g_edges[(size_t)r0 * CAP + 32 + lane];
        unsigned long long eh1 = g_edges[(size_t)r1 * CAP + 32 + lane];
        int t0 = deg0 - 32 > 0 ? deg0 - 32 : 0;
        int t1 = deg1 - 32 > 0 ? deg1 - 32 : 0;
        int mytb = (lane < 16) ? t0 : t1;
        int tmax = t0 > t1 ? t0 : t1;
        for (int j = 0; j < tmax; j++) {
            unsigned long long e0 = __shfl_sync(0xFFFFFFFFu, eh0, j);
            unsigned long long e1 = __shfl_sync(0xFFFFFFFFu, eh1, j);
            unsigned long long e  = (lane < 16) ? e0 : e1;
            bool act = j < mytb;
            unsigned c = act ? (unsigned)e : 0u;
            float    v = act ? __uint_as_float((unsigned)(e >> 32)) : 0.f;
            float4 s = sup4[c * 16u + hlane];
            acc.x += v * s.x; acc.y += v * s.y;
            acc.z += v * s.z; acc.w += v * s.w;
        }
    }

    float4 bv = reinterpret_cast<const float4*>(bias)[hlane];
    float h0 = acc.x + bv.x, h1 = acc.y + bv.y;
    float h2 = acc.z + bv.z, h3 = acc.w + bv.w;
    h0 = h0 > 0.f ? 2.f * h0 : 0.f;
    h1 = h1 > 0.f ? 2.f * h1 : 0.f;
    h2 = h2 > 0.f ? 2.f * h2 : 0.f;
    h3 = h3 > 0.f ? 2.f * h3 : 0.f;

    unsigned i0 = (unsigned)myrow * 64u + (unsigned)hlane * 4u;
    unsigned m0 = tf_hash(i0);
    unsigned m1 = tf_hash(i0 + 1u);
    unsigned m2 = tf_hash(i0 + 2u);
    unsigned m3 = tf_hash(i0 + 3u);

    float4 o;
    o.x = (m0 & 0x80000000u) ? 0.f : h0;
    o.y = (m1 & 0x80000000u) ? 0.f : h1;
    o.z = (m2 & 0x80000000u) ? 0.f : h2;
    o.w = (m3 & 0x80000000u) ? 0.f : h3;
    reinterpret_cast<float4*>(out)[(unsigned)myrow * 16u + hlane] = o;
}

// ---------------------------------------------------------------------------
extern "C" void kernel_launch(void* const* d_in, const int* in_sizes, int n_in,
                              void* d_out, int out_size) {
    const float* x    = (const float*)d_in[0];
    const int*   erow = (const int*)  d_in[1];
    const int*   ecol = (const int*)  d_in[2];
    const float* ev   = (const float*)d_in[3];
    const float* W    = (const float*)d_in[4];
    const float* b    = (const float*)d_in[5];
    float* out = (float*)d_out;

    build_kernel<<<6250, 256>>>(erow, ecol, ev);
    gemm_kernel <<<391, 256>>>(x, W);
    reduce_kernel<<<6250, 256>>>(out, b);
}